// round 15
// baseline (speedup 1.0000x reference)
#include <cuda_runtime.h>

#define B_   16
#define N_   1024
#define H_   224
#define W_   224
#define W2   112              // W_/2
#define KS   23
#define HALF 11
#define RPB  14               // output rows per block
#define TILES_Y 16            // H_/RPB
#define STRIP 36              // RPB+KS-1 hist rows
#define NTHR 256
#define NBLK (B_ * TILES_Y)   // 256 blocks

#define HIST_F (STRIP * W_)   // 8064 floats
#define BW     247            // odd row stride; 247%32=23 coprime -> conflict-free
#define B_F    (RPB * BW)     // 3458 floats
#define YRT    7              // y-conv rows per unit -> 2*112 = 224 units
#define XT     14             // x-conv cols per unit (7 packed pairs)
#define XTILES (W_ / XT)      // 16
#define XUNITS (RPB * XTILES) // 224 — one unit per thread, balanced

typedef unsigned long long u64;

// Compile-time Gaussian(sigma=3, ks=23), L1-normalized: exp(-(j-11)^2/18)/S.
__device__ constexpr float WT[KS] = {
    0.00016011f, 0.00051415f, 0.00147746f, 0.00379911f, 0.00874165f,
    0.01799911f, 0.03316293f, 0.05467645f, 0.08066640f, 0.10649510f,
    0.12580922f, 0.13299641f, 0.12580922f, 0.10649510f, 0.08066640f,
    0.05467645f, 0.03316293f, 0.01799911f, 0.00874165f, 0.00379911f,
    0.00147746f, 0.00051415f, 0.00016011f
};

__device__ __forceinline__ void ffma2(u64& acc, u64 a, u64 b) {
    asm("fma.rn.f32x2 %0, %1, %2, %0;" : "+l"(acc) : "l"(a), "l"(b));
}
__device__ __forceinline__ u64 pack2(float lo, float hi) {
    u64 r;
    asm("mov.b64 %0, {%1, %2};"
        : "=l"(r) : "r"(__float_as_uint(lo)), "r"(__float_as_uint(hi)));
    return r;
}
__device__ __forceinline__ float2 unpack2(u64 v) {
    float2 r;
    asm("mov.b64 {%0, %1}, %2;" : "=f"(r.x), "=f"(r.y) : "l"(v));
    return r;
}

__global__ void __launch_bounds__(NTHR, 4)
saliency_kernel(const float* __restrict__ points, float* __restrict__ out) {
    __shared__ __align__(16) float s_hist[HIST_F];  // [STRIP][W_]
    __shared__ __align__(16) float s_B[B_F];        // [RPB][BW], cols [0..10] halo=0
    __shared__ u64   s_w2[KS];   // {w[j], w[j]}
    __shared__ u64   s_wp[KS+1]; // {w[u], w[u-1]}, u in 0..23 (edges zero-padded)

    const int tidx = threadIdx.x;
    const int b    = blockIdx.x / TILES_Y;
    const int tile = blockIdx.x % TILES_Y;
    const int r0   = tile * RPB;
    const int ylo  = r0 - HALF;                     // hist row 0 == global row ylo

    // ---- Prefetch this thread's 4 points (2 float4 = 4 (x,y) pairs) ----
    const float4* p4 = reinterpret_cast<const float4*>(points + b * N_ * 2);
    float4 pa = p4[tidx];
    float4 pb = p4[tidx + NTHR];

    // ---- Phase 0: zero hist + B, fill packed weight tables from constants ----
    {
        float4 z4 = make_float4(0.f, 0.f, 0.f, 0.f);
        float4* h4 = reinterpret_cast<float4*>(s_hist);
        #pragma unroll
        for (int k = tidx; k < HIST_F / 4; k += NTHR) h4[k] = z4;
        float2 z2 = make_float2(0.f, 0.f);
        float2* b2 = reinterpret_cast<float2*>(s_B);
        #pragma unroll
        for (int k = tidx; k < B_F / 2; k += NTHR) b2[k] = z2;
    }
    if (tidx < KS) s_w2[tidx] = pack2(WT[tidx], WT[tidx]);
    if (tidx <= KS) {
        float lo = (tidx < KS) ? WT[tidx] : 0.f;
        float hi = (tidx >= 1) ? WT[tidx - 1] : 0.f;
        s_wp[tidx] = pack2(lo, hi);
    }
    __syncthreads();

    // ---- Phase 1: histogram scatter — one smem atomic per matching point ----
    {
        #pragma unroll
        for (int q = 0; q < 4; q++) {
            float px = (q == 0) ? pa.x : (q == 1) ? pa.z : (q == 2) ? pb.x : pb.z;
            float py = (q == 0) ? pa.y : (q == 1) ? pa.w : (q == 2) ? pb.y : pb.w;
            int x = (int)(px * (float)W_);  // truncation == astype(int32), nonneg
            int y = (int)(py * (float)H_);
            int u = y - ylo;
            if ((unsigned)u < (unsigned)STRIP &&
                (unsigned)x < (unsigned)W_ && (unsigned)y < (unsigned)H_)
                atomicAdd(&s_hist[u * W_ + x], 1.0f);
        }
    }
    __syncthreads();

    // ---- Phase 2: y-conv, float2 cols, 7-row register tile, FFMA2 ----
    if (tidx < 2 * W2) {                            // 224 units, balanced
        int c2  = tidx % W2;
        int rl0 = (tidx / W2) * YRT;

        const u64* h2 = reinterpret_cast<const u64*>(s_hist);
        u64 acc[YRT];
        #pragma unroll
        for (int k = 0; k < YRT; k++) acc[k] = 0ull;
        u64 wv[YRT];
        #pragma unroll
        for (int k = 0; k < YRT; k++) wv[k] = 0ull;

        #pragma unroll
        for (int u = 0; u < YRT + KS - 1; u++) {    // 29 strip rows
            #pragma unroll
            for (int k = YRT - 1; k >= 1; k--) wv[k] = wv[k - 1];  // renamed
            if (u < KS) wv[0] = s_w2[u];                           // LDS.64 bcast
            u64 v2 = h2[(rl0 + u) * W2 + c2];
            #pragma unroll
            for (int k = 0; k < YRT; k++) {
                int j = u - k;                      // compile-time per (u,k)
                if (j >= 0 && j < KS) ffma2(acc[k], wv[k], v2);
            }
        }
        #pragma unroll
        for (int k = 0; k < YRT; k++) {
            float2 a = unpack2(acc[k]);
            float* dst = s_B + (rl0 + k) * BW + HALF + c2 * 2;
            dst[0] = a.x;
            dst[1] = a.y;
        }
    }
    __syncthreads();

    // ---- Phase 3: x-conv, 14 cols per unit (7 packed pairs), single pass ----
    // acc[k] = {out[c0+2k], out[c0+2k+1]}; pair weight wv[2k] == s_wp[u-2k]
    if (tidx < XUNITS) {                            // 224 units, balanced
        int r  = tidx % RPB;
        int ct = tidx / RPB;
        int c0 = ct * XT;

        const float* brow = s_B + r * BW + c0;      // brow[u] == input col c0+u-11
        u64 acc[XT / 2];
        #pragma unroll
        for (int k = 0; k < XT / 2; k++) acc[k] = 0ull;
        u64 wv[XT - 1];                             // 13-deep packed window
        #pragma unroll
        for (int k = 0; k < XT - 1; k++) wv[k] = 0ull;

        #pragma unroll
        for (int u = 0; u < XT + KS - 1; u++) {     // 36 taps window
            #pragma unroll
            for (int k = XT - 2; k >= 1; k--) wv[k] = wv[k - 1];  // renamed
            if (u <= KS) wv[0] = s_wp[u];            // broadcast, 24 entries
            float v = brow[u];
            u64 vv = pack2(v, v);
            #pragma unroll
            for (int k = 0; k < XT / 2; k++) {
                int up = u - 2 * k;                  // wv[2k] == s_wp[u-2k]
                if (up >= 0 && up <= KS) ffma2(acc[k], wv[2 * k], vv);
            }
        }

        float* orow = out + (b * H_ + r0 + r) * W_ + c0;  // 8B-aligned (c0 even)
        #pragma unroll
        for (int k = 0; k < XT / 2; k++) {
            float2 a = unpack2(acc[k]);
            reinterpret_cast<float2*>(orow)[k] = a;
        }
    }
}

extern "C" void kernel_launch(void* const* d_in, const int* in_sizes, int n_in,
                              void* d_out, int out_size) {
    const float* points = (const float*)d_in[1];  // d_in[0] = feature_map (unused)
    float* out = (float*)d_out;
    saliency_kernel<<<NBLK, NTHR>>>(points, out);
}

// round 16
// speedup vs baseline: 1.2667x; 1.2667x over previous
#include <cuda_runtime.h>

#define B_   16
#define N_   1024
#define H_   224
#define W_   224
#define W2   112              // W_/2
#define KS   23
#define HALF 11
#define RPB  14               // output rows per block
#define TILES_Y 16            // H_/RPB
#define STRIP 36              // RPB+KS-1 hist rows
#define NTHR 384
#define NBLK (B_ * TILES_Y)   // 256 blocks

#define HIST_F (STRIP * W_)   // 8064 floats
#define BW     247            // odd row stride; 247%32=23 coprime -> conflict-free
#define B_F    (RPB * BW)     // 3458 floats
#define YRT    7              // y-conv rows per unit -> 2*112 = 224 units
#define XT     8              // x-conv cols per unit (4 packed pairs) — proven best
#define XTILES (W_ / XT)      // 28
#define XUNITS (RPB * XTILES) // 392 — ~1 per thread at NTHR=384

typedef unsigned long long u64;

// Compile-time Gaussian(sigma=3, ks=23), L1-normalized: exp(-(j-11)^2/18)/S.
__device__ constexpr float WT[KS] = {
    0.00016011f, 0.00051415f, 0.00147746f, 0.00379911f, 0.00874165f,
    0.01799911f, 0.03316293f, 0.05467645f, 0.08066640f, 0.10649510f,
    0.12580922f, 0.13299641f, 0.12580922f, 0.10649510f, 0.08066640f,
    0.05467645f, 0.03316293f, 0.01799911f, 0.00874165f, 0.00379911f,
    0.00147746f, 0.00051415f, 0.00016011f
};

__device__ __forceinline__ void ffma2(u64& acc, u64 a, u64 b) {
    asm("fma.rn.f32x2 %0, %1, %2, %0;" : "+l"(acc) : "l"(a), "l"(b));
}
__device__ __forceinline__ u64 pack2(float lo, float hi) {
    u64 r;
    asm("mov.b64 %0, {%1, %2};"
        : "=l"(r) : "r"(__float_as_uint(lo)), "r"(__float_as_uint(hi)));
    return r;
}
__device__ __forceinline__ float2 unpack2(u64 v) {
    float2 r;
    asm("mov.b64 {%0, %1}, %2;" : "=f"(r.x), "=f"(r.y) : "l"(v));
    return r;
}

__global__ void __launch_bounds__(NTHR, 2)
saliency_kernel(const float* __restrict__ points, float* __restrict__ out) {
    __shared__ __align__(16) float s_hist[HIST_F];  // [STRIP][W_]
    __shared__ __align__(16) float s_B[B_F];        // [RPB][BW], cols [0..10] halo=0
    __shared__ u64   s_w2[KS];   // {w[j], w[j]}
    __shared__ u64   s_wp[KS+1]; // {w[u], w[u-1]}, u in 0..23 (edges zero-padded)

    const int tidx = threadIdx.x;
    const int b    = blockIdx.x / TILES_Y;
    const int tile = blockIdx.x % TILES_Y;
    const int r0   = tile * RPB;
    const int ylo  = r0 - HALF;                     // hist row 0 == global row ylo

    // ---- Prefetch 4 points each for the first 256 threads ----
    const float4* p4 = reinterpret_cast<const float4*>(points + b * N_ * 2);
    float4 pa = make_float4(0.f, 2.f, 0.f, 2.f);    // y=2*H -> guaranteed out of strip
    float4 pb = pa;
    if (tidx < 256) {
        pa = p4[tidx];
        pb = p4[tidx + 256];
    }

    // ---- Phase 0: zero hist + B, fill packed weight tables from constants ----
    {
        float4 z4 = make_float4(0.f, 0.f, 0.f, 0.f);
        float4* h4 = reinterpret_cast<float4*>(s_hist);
        #pragma unroll
        for (int k = tidx; k < HIST_F / 4; k += NTHR) h4[k] = z4;
        float2 z2 = make_float2(0.f, 0.f);
        float2* b2 = reinterpret_cast<float2*>(s_B);
        #pragma unroll
        for (int k = tidx; k < B_F / 2; k += NTHR) b2[k] = z2;
    }
    if (tidx < KS) s_w2[tidx] = pack2(WT[tidx], WT[tidx]);
    if (tidx <= KS) {
        float lo = (tidx < KS) ? WT[tidx] : 0.f;
        float hi = (tidx >= 1) ? WT[tidx - 1] : 0.f;
        s_wp[tidx] = pack2(lo, hi);
    }
    __syncthreads();

    // ---- Phase 1: histogram scatter — one smem atomic per matching point ----
    {
        #pragma unroll
        for (int q = 0; q < 4; q++) {
            float px = (q == 0) ? pa.x : (q == 1) ? pa.z : (q == 2) ? pb.x : pb.z;
            float py = (q == 0) ? pa.y : (q == 1) ? pa.w : (q == 2) ? pb.y : pb.w;
            int x = (int)(px * (float)W_);  // truncation == astype(int32), nonneg
            int y = (int)(py * (float)H_);
            int u = y - ylo;
            if ((unsigned)u < (unsigned)STRIP &&
                (unsigned)x < (unsigned)W_ && (unsigned)y < (unsigned)H_)
                atomicAdd(&s_hist[u * W_ + x], 1.0f);
        }
    }
    __syncthreads();

    // ---- Phase 2: y-conv, float2 cols, 7-row register tile, FFMA2 ----
    if (tidx < 2 * W2) {                            // 224 units
        int c2  = tidx % W2;
        int rl0 = (tidx / W2) * YRT;

        const u64* h2 = reinterpret_cast<const u64*>(s_hist);
        u64 acc[YRT];
        #pragma unroll
        for (int k = 0; k < YRT; k++) acc[k] = 0ull;
        u64 wv[YRT];
        #pragma unroll
        for (int k = 0; k < YRT; k++) wv[k] = 0ull;

        #pragma unroll
        for (int u = 0; u < YRT + KS - 1; u++) {    // 29 strip rows
            #pragma unroll
            for (int k = YRT - 1; k >= 1; k--) wv[k] = wv[k - 1];  // renamed
            if (u < KS) wv[0] = s_w2[u];                           // LDS.64 bcast
            u64 v2 = h2[(rl0 + u) * W2 + c2];
            #pragma unroll
            for (int k = 0; k < YRT; k++) {
                int j = u - k;                      // compile-time per (u,k)
                if (j >= 0 && j < KS) ffma2(acc[k], wv[k], v2);
            }
        }
        #pragma unroll
        for (int k = 0; k < YRT; k++) {
            float2 a = unpack2(acc[k]);
            float* dst = s_B + (rl0 + k) * BW + HALF + c2 * 2;
            dst[0] = a.x;
            dst[1] = a.y;
        }
    }
    __syncthreads();

    // ---- Phase 3: x-conv, XT=8 packed pairs; 392 units over 384 threads ----
    #pragma unroll
    for (int it = 0; it < 2; it++) {
        int unit = tidx + it * NTHR;
        if (unit < XUNITS) {
            int r  = unit % RPB;         // row-major: lane stride = BW (coprime 32)
            int ct = unit / RPB;
            int c0 = ct * XT;

            const float* brow = s_B + r * BW + c0;  // brow[u] == input col c0+u-11
            u64 acc[XT / 2];
            #pragma unroll
            for (int k = 0; k < XT / 2; k++) acc[k] = 0ull;
            u64 wv[XT - 1];
            #pragma unroll
            for (int k = 0; k < XT - 1; k++) wv[k] = 0ull;

            #pragma unroll
            for (int u = 0; u < XT + KS - 1; u++) {   // 30 taps window
                #pragma unroll
                for (int k = XT - 2; k >= 1; k--) wv[k] = wv[k - 1];
                if (u <= KS) wv[0] = s_wp[u];          // broadcast, 24 entries
                float v = brow[u];
                u64 vv = pack2(v, v);
                #pragma unroll
                for (int k = 0; k < XT / 2; k++) {
                    int up = u - 2 * k;                // wv[2k] == s_wp[u-2k]
                    if (up >= 0 && up <= KS) ffma2(acc[k], wv[2 * k], vv);
                }
            }

            float2 a0 = unpack2(acc[0]);
            float2 a1 = unpack2(acc[1]);
            float2 a2 = unpack2(acc[2]);
            float2 a3 = unpack2(acc[3]);
            float* orow = out + (b * H_ + r0 + r) * W_ + c0;
            reinterpret_cast<float4*>(orow)[0] = make_float4(a0.x, a0.y, a1.x, a1.y);
            reinterpret_cast<float4*>(orow)[1] = make_float4(a2.x, a2.y, a3.x, a3.y);
        }
    }
}

extern "C" void kernel_launch(void* const* d_in, const int* in_sizes, int n_in,
                              void* d_out, int out_size) {
    const float* points = (const float*)d_in[1];  // d_in[0] = feature_map (unused)
    float* out = (float*)d_out;
    saliency_kernel<<<NBLK, NTHR>>>(points, out);
}